// round 1
// baseline (speedup 1.0000x reference)
#include <cuda_runtime.h>
#include <math.h>

#define EMB   1024
#define HID   2048
#define VOCAB 50257
#define T     256

// Persistent device state (allocation-free scratch).
__device__ float g_h[2][HID];              // double-buffered hidden state
__device__ float g_c[HID];                 // cell state
__device__ unsigned long long g_amax[T];   // packed argmax accumulator per step

// ---------------------------------------------------------------------------
// Init: zero h (both buffers), c, and the argmax slots. Runs once per launch
// so replays are deterministic.
// ---------------------------------------------------------------------------
__global__ void init_kernel() {
    int i = blockIdx.x * blockDim.x + threadIdx.x;
    if (i < HID) {
        g_h[0][i] = 0.0f;
        g_h[1][i] = 0.0f;
        g_c[i]    = 0.0f;
    }
    if (i < T) g_amax[i] = 0ULL;
}

// ---------------------------------------------------------------------------
// Step kernel: gates = W_ih @ x + b_ih + W_hh @ h + b_hh, then LSTM cell.
// One warp per hidden index j; the warp computes all 4 gate rows.
// Grid: 256 blocks x 256 threads (8 warps/block -> 8 j per block).
// h is double buffered: read g_h[step&1], write g_h[(step+1)&1].
// ---------------------------------------------------------------------------
__global__ void __launch_bounds__(256) lstm_step_kernel(
    const float* __restrict__ emb,
    const float* __restrict__ W_ih,
    const float* __restrict__ W_hh,
    const float* __restrict__ b_ih,
    const float* __restrict__ b_hh,
    int step)
{
    __shared__ float sx[EMB];
    __shared__ float sh[HID];

    // Decode previous token from packed argmax (tok=0 at step 0).
    int tok = 0;
    if (step > 0) {
        unsigned long long key = g_amax[step - 1];
        tok = (int)(0xFFFFFFFFu - (unsigned)(key & 0xFFFFFFFFull));
    }

    const float* __restrict__ hprev = g_h[step & 1];
    float* __restrict__ hnext       = g_h[(step + 1) & 1];

    const float* __restrict__ xrow = emb + (size_t)tok * EMB;
    for (int i = threadIdx.x; i < EMB; i += blockDim.x) sx[i] = xrow[i];
    for (int i = threadIdx.x; i < HID; i += blockDim.x) sh[i] = hprev[i];
    __syncthreads();

    const int warp = threadIdx.x >> 5;
    const int lane = threadIdx.x & 31;
    const int j    = blockIdx.x * 8 + warp;   // 0..2047

    float acc0 = 0.f, acc1 = 0.f, acc2 = 0.f, acc3 = 0.f;

    const float4* __restrict__ s4x = (const float4*)sx;
    const float4* __restrict__ s4h = (const float4*)sh;

    #pragma unroll
    for (int g = 0; g < 4; g++) {
        const int row = g * HID + j;
        float a = 0.f;

        const float4* __restrict__ w1 = (const float4*)(W_ih + (size_t)row * EMB);
        #pragma unroll
        for (int k = 0; k < EMB / 128; k++) {          // 8 iters
            float4 w = w1[lane + 32 * k];
            float4 v = s4x[lane + 32 * k];
            a += w.x * v.x + w.y * v.y + w.z * v.z + w.w * v.w;
        }

        const float4* __restrict__ w2 = (const float4*)(W_hh + (size_t)row * HID);
        #pragma unroll
        for (int k = 0; k < HID / 128; k++) {          // 16 iters
            float4 w = w2[lane + 32 * k];
            float4 v = s4h[lane + 32 * k];
            a += w.x * v.x + w.y * v.y + w.z * v.z + w.w * v.w;
        }

        if (g == 0) acc0 = a;
        else if (g == 1) acc1 = a;
        else if (g == 2) acc2 = a;
        else acc3 = a;
    }

    #pragma unroll
    for (int off = 16; off; off >>= 1) {
        acc0 += __shfl_down_sync(0xFFFFFFFFu, acc0, off);
        acc1 += __shfl_down_sync(0xFFFFFFFFu, acc1, off);
        acc2 += __shfl_down_sync(0xFFFFFFFFu, acc2, off);
        acc3 += __shfl_down_sync(0xFFFFFFFFu, acc3, off);
    }

    if (lane == 0) {
        float ipre = acc0 + b_ih[j]           + b_hh[j];
        float fpre = acc1 + b_ih[HID + j]     + b_hh[HID + j];
        float gpre = acc2 + b_ih[2 * HID + j] + b_hh[2 * HID + j];
        float opre = acc3 + b_ih[3 * HID + j] + b_hh[3 * HID + j];

        float ig = 1.0f / (1.0f + expf(-ipre));
        float fg = 1.0f / (1.0f + expf(-fpre));
        float gg = tanhf(gpre);
        float og = 1.0f / (1.0f + expf(-opre));

        float c = fg * g_c[j] + ig * gg;
        g_c[j]   = c;
        hnext[j] = og * tanhf(c);
    }
}

// ---------------------------------------------------------------------------
// Logits kernel: logits[v] = dot(W_out[v], h) + b_out[v], write to out,
// and fold a global argmax via packed atomicMax (first-index tie like
// jnp.argmax: key = orderable(value)<<32 | (0xFFFFFFFF - idx)).
// Warp-per-row; 8 rows per 256-thread block.
// ---------------------------------------------------------------------------
__global__ void __launch_bounds__(256) logits_kernel(
    const float* __restrict__ W_out,
    const float* __restrict__ b_out,
    float* __restrict__ out,
    int step)
{
    __shared__ float sh[HID];
    __shared__ unsigned long long blockbest;

    const float* __restrict__ h = g_h[(step + 1) & 1];
    for (int i = threadIdx.x; i < HID; i += blockDim.x) sh[i] = h[i];
    if (threadIdx.x == 0) blockbest = 0ULL;
    __syncthreads();

    const int warp = threadIdx.x >> 5;
    const int lane = threadIdx.x & 31;
    const int row  = blockIdx.x * 8 + warp;

    if (row < VOCAB) {
        const float4* __restrict__ w  = (const float4*)(W_out + (size_t)row * HID);
        const float4* __restrict__ s4 = (const float4*)sh;

        float a = 0.f;
        #pragma unroll
        for (int k = 0; k < HID / 128; k++) {          // 16 iters
            float4 wv = w[lane + 32 * k];
            float4 hv = s4[lane + 32 * k];
            a += wv.x * hv.x + wv.y * hv.y + wv.z * hv.z + wv.w * hv.w;
        }

        #pragma unroll
        for (int off = 16; off; off >>= 1)
            a += __shfl_down_sync(0xFFFFFFFFu, a, off);

        if (lane == 0) {
            float logit = a + b_out[row];
            out[(size_t)step * VOCAB + row] = logit;

            unsigned ub = __float_as_uint(logit);
            ub = (ub & 0x80000000u) ? ~ub : (ub | 0x80000000u);
            unsigned long long key =
                ((unsigned long long)ub << 32) | (unsigned long long)(0xFFFFFFFFu - (unsigned)row);
            atomicMax(&blockbest, key);
        }
    }
    __syncthreads();

    if (threadIdx.x == 0 && blockbest != 0ULL)
        atomicMax(&g_amax[step], blockbest);
}

// ---------------------------------------------------------------------------
// kernel_launch: init + 256 x (step, logits) on one stream (graph-capturable).
// Inputs (metadata order): emb, W_ih, W_hh, b_ih, b_hh, W_out, b_out.
// ---------------------------------------------------------------------------
extern "C" void kernel_launch(void* const* d_in, const int* in_sizes, int n_in,
                              void* d_out, int out_size) {
    const float* emb   = (const float*)d_in[0];
    const float* W_ih  = (const float*)d_in[1];
    const float* W_hh  = (const float*)d_in[2];
    const float* b_ih  = (const float*)d_in[3];
    const float* b_hh  = (const float*)d_in[4];
    const float* W_out = (const float*)d_in[5];
    const float* b_out = (const float*)d_in[6];
    float* out = (float*)d_out;

    init_kernel<<<(HID + 255) / 256, 256>>>();

    for (int t = 0; t < T; t++) {
        lstm_step_kernel<<<HID / 8, 256>>>(emb, W_ih, W_hh, b_ih, b_hh, t);
        logits_kernel<<<(VOCAB + 7) / 8, 256>>>(W_out, b_out, out, t);
    }
}